// round 6
// baseline (speedup 1.0000x reference)
#include <cuda_runtime.h>
#include <stdint.h>

typedef unsigned long long u64;

// ---- packed fp32x2 primitives (SASS FFMA2 path, 2x fp32 throughput) ----
__device__ __forceinline__ u64 fma2(u64 a, u64 b, u64 c) {
    u64 d; asm("fma.rn.f32x2 %0, %1, %2, %3;" : "=l"(d) : "l"(a), "l"(b), "l"(c)); return d;
}
__device__ __forceinline__ u64 mul2(u64 a, u64 b) {
    u64 d; asm("mul.rn.f32x2 %0, %1, %2;" : "=l"(d) : "l"(a), "l"(b)); return d;
}
__device__ __forceinline__ u64 pack2(float lo, float hi) {
    u64 d; asm("mov.b64 %0, {%1, %2};" : "=l"(d) : "f"(lo), "f"(hi)); return d;
}
__device__ __forceinline__ void unpack2(u64 v, float& lo, float& hi) {
    asm("mov.b64 {%0, %1}, %2;" : "=f"(lo), "=f"(hi) : "l"(v));
}

// leaky(x) = max(x, 0.01x)  (exact elementwise for slope<1)
__device__ __forceinline__ u64 leaky2(u64 x) {
    const u64 SL = 0x3C23D70A3C23D70AULL;  // (0.01f, 0.01f)
    u64 s = mul2(x, SL);
    float xl, xh, sl, sh;
    unpack2(x, xl, xh); unpack2(s, sl, sh);
    return pack2(fmaxf(xl, sl), fmaxf(xh, sh));
}

struct Params { const float* p[20]; };  // [0..4]=ws_logs [5..9]=bs_logs [10..14]=ws_b [15..19]=bs_b

// Packed duplicated weights in GLOBAL memory (written once by prologue kernel).
// Warp-uniform LDG reads: one 16B sector per access -> off the smem-broadcast path.
__device__ ulonglong2 GW[2][5][32];   // [(w2i,w2i),(w2i+1,w2i+1)] granules
__device__ ulonglong2 GB[2][5][4];    // bias dup-pairs

__global__ void pack_params_kernel(Params P)
{
    int tid = threadIdx.x;
    for (int idx = tid; idx < 320; idx += blockDim.x) {
        int m = idx / 160, r = idx % 160, l = r / 32, k = r % 32;
        int j = k / 4, i2 = k % 4;
        const float* Wp = P.p[m * 10 + l];
        float w0 = Wp[j * 8 + i2 * 2], w1 = Wp[j * 8 + i2 * 2 + 1];
        GW[m][l][k] = make_ulonglong2(pack2(w0, w0), pack2(w1, w1));
    }
    for (int idx = tid; idx < 40; idx += blockDim.x) {
        int m = idx / 20, r = idx % 20, l = r / 4, k = r % 4;
        const float* Bp = P.p[m * 10 + 5 + l];
        float b0 = Bp[2 * k], b1 = Bp[2 * k + 1];
        GB[m][l][k] = make_ulonglong2(pack2(b0, b0), pack2(b1, b1));
    }
}

// One 8->8 layer on TWO packed row-pairs; weights via uniform global LDG.128.
__device__ __forceinline__ void layer2pairG(
    const ulonglong2* __restrict__ W, const ulonglong2* __restrict__ Bq,
    const u64* in0, const u64* in1, u64* out0, u64* out1, bool act)
{
#pragma unroll
    for (int j2 = 0; j2 < 4; j2++) {
        ulonglong2 bias = Bq[j2];
        u64 a0 = bias.x, a1 = bias.x;           // row j = 2*j2
        u64 c0 = bias.y, c1 = bias.y;           // row j = 2*j2+1
#pragma unroll
        for (int i2 = 0; i2 < 4; i2++) {
            ulonglong2 wa = W[(2 * j2)     * 4 + i2];
            ulonglong2 wc = W[(2 * j2 + 1) * 4 + i2];
            a0 = fma2(wa.x, in0[2 * i2],     a0);
            a1 = fma2(wa.x, in1[2 * i2],     a1);
            a0 = fma2(wa.y, in0[2 * i2 + 1], a0);
            a1 = fma2(wa.y, in1[2 * i2 + 1], a1);
            c0 = fma2(wc.x, in0[2 * i2],     c0);
            c1 = fma2(wc.x, in1[2 * i2],     c1);
            c0 = fma2(wc.y, in0[2 * i2 + 1], c0);
            c1 = fma2(wc.y, in1[2 * i2 + 1], c1);
        }
        out0[2 * j2]     = act ? leaky2(a0) : a0;
        out1[2 * j2]     = act ? leaky2(a1) : a1;
        out0[2 * j2 + 1] = act ? leaky2(c0) : c0;
        out1[2 * j2 + 1] = act ? leaky2(c1) : c1;
    }
}

template <int IOW>
__device__ __forceinline__ float4 ld4(const float* p) {
    if (IOW == 4) return *(const float4*)p;
    else if (IOW == 2) { float2 u = *(const float2*)p, v = *(const float2*)(p + 2);
                         return make_float4(u.x, u.y, v.x, v.y); }
    else return make_float4(p[0], p[1], p[2], p[3]);
}
template <int IOW>
__device__ __forceinline__ void st4(float* p, float4 v) {
    if (IOW == 4) *(float4*)p = v;
    else if (IOW == 2) { *(float2*)p = make_float2(v.x, v.y);
                         *(float2*)(p + 2) = make_float2(v.z, v.w); }
    else { p[0] = v.x; p[1] = v.y; p[2] = v.z; p[3] = v.w; }
}

// IOW: I/O width in floats per memory op (4 = float4, 2 = float2, 1 = scalar)
template <int IOW>
__global__ __launch_bounds__(128, 4)
void affine_coupling_kernel(const float* __restrict__ z, float* __restrict__ out,
                            int batch)
{
    const int tid = threadIdx.x;
    const int lane = tid & 31;
    const int warp = tid >> 5;
    long long warpBase = ((long long)blockIdx.x * 4 + warp) * 128;
    if (warpBase >= batch) return;  // batch % 128 == 0 -> active warps are full

    // Each thread: 2 pairs = 4 rows. Pair p = (warpBase + 64p + lane, +32).
    int rA[2], rB[2];
    u64 zl[2][8];
#pragma unroll
    for (int p = 0; p < 2; p++) {
        rA[p] = (int)warpBase + p * 64 + lane;
        rB[p] = rA[p] + 32;
        const float* pa = z + (long long)rA[p] * 16;
        const float* pb = z + (long long)rB[p] * 16;
        // front halves only (zr deferred to epilogue to cut live registers)
        float4 a0 = ld4<IOW>(pa), a1 = ld4<IOW>(pa + 4);
        float4 b0 = ld4<IOW>(pb), b1 = ld4<IOW>(pb + 4);

        // left-half passthrough: store immediately
        float* oa = out + (long long)rA[p] * 16;
        float* ob = out + (long long)rB[p] * 16;
        st4<IOW>(oa, a0);     st4<IOW>(oa + 4, a1);
        st4<IOW>(ob, b0);     st4<IOW>(ob + 4, b1);

        zl[p][0] = pack2(a0.x, b0.x); zl[p][1] = pack2(a0.y, b0.y);
        zl[p][2] = pack2(a0.z, b0.z); zl[p][3] = pack2(a0.w, b0.w);
        zl[p][4] = pack2(a1.x, b1.x); zl[p][5] = pack2(a1.y, b1.y);
        zl[p][6] = pack2(a1.z, b1.z); zl[p][7] = pack2(a1.w, b1.w);
    }

    u64 s[2][8], t[2][8];

    // ---- log_s chain (m=0); zl stays alive for the b chain ----
    layer2pairG(GW[0][0], GB[0][0], zl[0], zl[1], s[0], s[1], true);
    layer2pairG(GW[0][1], GB[0][1], s[0], s[1], t[0], t[1], true);
    layer2pairG(GW[0][2], GB[0][2], t[0], t[1], s[0], s[1], true);
    layer2pairG(GW[0][3], GB[0][3], s[0], s[1], t[0], t[1], true);
    u64 ls[2][8];
    layer2pairG(GW[0][4], GB[0][4], t[0], t[1], ls[0], ls[1], false);

    // convert to exp(log_s), packed (reuses ls registers)
    u64 els[2][8];
#pragma unroll
    for (int p = 0; p < 2; p++)
#pragma unroll
        for (int j = 0; j < 8; j++) {
            float lA, lB; unpack2(ls[p][j], lA, lB);
            els[p][j] = pack2(__expf(lA), __expf(lB));
        }

    // ---- b chain (m=1); zl dies after layer 0 ----
    layer2pairG(GW[1][0], GB[1][0], zl[0], zl[1], s[0], s[1], true);
    layer2pairG(GW[1][1], GB[1][1], s[0], s[1], t[0], t[1], true);
    layer2pairG(GW[1][2], GB[1][2], t[0], t[1], s[0], s[1], true);
    layer2pairG(GW[1][3], GB[1][3], s[0], s[1], t[0], t[1], true);
    u64 bv[2][8];
    layer2pairG(GW[1][4], GB[1][4], t[0], t[1], bv[0], bv[1], false);

    // ---- epilogue: load zr now, yr = exp(log_s) * zr + b ----
#pragma unroll
    for (int p = 0; p < 2; p++) {
        const float* pa = z + (long long)rA[p] * 16 + 8;
        const float* pb = z + (long long)rB[p] * 16 + 8;
        float4 a2 = ld4<IOW>(pa), a3 = ld4<IOW>(pa + 4);
        float4 b2 = ld4<IOW>(pb), b3 = ld4<IOW>(pb + 4);

        u64 zr[8];
        zr[0] = pack2(a2.x, b2.x); zr[1] = pack2(a2.y, b2.y);
        zr[2] = pack2(a2.z, b2.z); zr[3] = pack2(a2.w, b2.w);
        zr[4] = pack2(a3.x, b3.x); zr[5] = pack2(a3.y, b3.y);
        zr[6] = pack2(a3.z, b3.z); zr[7] = pack2(a3.w, b3.w);

        float yA[8], yB[8];
#pragma unroll
        for (int j = 0; j < 8; j++) {
            u64 y = fma2(els[p][j], zr[j], bv[p][j]);
            unpack2(y, yA[j], yB[j]);
        }
        float* oa = out + (long long)rA[p] * 16 + 8;
        float* ob = out + (long long)rB[p] * 16 + 8;
        st4<IOW>(oa,     make_float4(yA[0], yA[1], yA[2], yA[3]));
        st4<IOW>(oa + 4, make_float4(yA[4], yA[5], yA[6], yA[7]));
        st4<IOW>(ob,     make_float4(yB[0], yB[1], yB[2], yB[3]));
        st4<IOW>(ob + 4, make_float4(yB[4], yB[5], yB[6], yB[7]));
    }
}

extern "C" void kernel_launch(void* const* d_in, const int* in_sizes, int n_in,
                              void* d_out, int out_size)
{
    // ---- locate z: the (unique) huge input ----
    int zi = 0;
    for (int i = 0; i < n_in; i++) {
        if (in_sizes[i] > in_sizes[zi]) zi = i;
    }
    const float* z = (const float*)d_in[zi];
    long long batchLL = (long long)in_sizes[zi] / 16;
    int batch = (int)batchLL;
    float* out = (float*)d_out;

    // ---- build the 20 layer-parameter pointers, layout-adaptively ----
    Params P;
    if (n_in >= 21) {
        int k = 0;
        for (int i = 0; i < n_in && k < 20; i++) {
            if (i == zi) continue;
            P.p[k++] = (const float*)d_in[i];
        }
    } else {
        int wslot = 0, bslot = 0;  // 0 -> logs, 1 -> b
        for (int i = 0; i < n_in; i++) {
            if (i == zi) continue;
            const float* base = (const float*)d_in[i];
            int sz = in_sizes[i];
            if (sz == 320) {            // stacked weights (5,8,8)
                int m = (wslot++ == 0) ? 0 : 1;
                for (int l = 0; l < 5; l++) P.p[m * 10 + l] = base + 64 * l;
            } else if (sz == 40) {      // stacked biases (5,8)
                int m = (bslot++ == 0) ? 0 : 1;
                for (int l = 0; l < 5; l++) P.p[m * 10 + 5 + l] = base + 8 * l;
            }
        }
    }

    // prologue: pack duplicated weight pairs into global scratch (graph-captured)
    pack_params_kernel<<<1, 128>>>(P);

    int rowsPerBlock = 512;                // 128 threads * 4 rows
    int grid = (int)((batchLL + rowsPerBlock - 1) / rowsPerBlock);

    uintptr_t mis = (uintptr_t)z | (uintptr_t)out;
    if ((mis & 15) == 0) {
        affine_coupling_kernel<4><<<grid, 128>>>(z, out, batch);
    } else if ((mis & 7) == 0) {
        affine_coupling_kernel<2><<<grid, 128>>>(z, out, batch);
    } else {
        affine_coupling_kernel<1><<<grid, 128>>>(z, out, batch);
    }
}

// round 8
// speedup vs baseline: 1.7798x; 1.7798x over previous
#include <cuda_runtime.h>
#include <stdint.h>

typedef unsigned long long u64;

// ---- packed fp32x2 primitives (SASS FFMA2 path, 2x fp32 throughput) ----
__device__ __forceinline__ u64 fma2(u64 a, u64 b, u64 c) {
    u64 d; asm("fma.rn.f32x2 %0, %1, %2, %3;" : "=l"(d) : "l"(a), "l"(b), "l"(c)); return d;
}
__device__ __forceinline__ u64 mul2(u64 a, u64 b) {
    u64 d; asm("mul.rn.f32x2 %0, %1, %2;" : "=l"(d) : "l"(a), "l"(b)); return d;
}
__device__ __forceinline__ u64 pack2(float lo, float hi) {
    u64 d; asm("mov.b64 %0, {%1, %2};" : "=l"(d) : "f"(lo), "f"(hi)); return d;
}
__device__ __forceinline__ void unpack2(u64 v, float& lo, float& hi) {
    asm("mov.b64 {%0, %1}, %2;" : "=f"(lo), "=f"(hi) : "l"(v));
}

// leaky(x) = max(x, 0.01x)  (exact elementwise for slope<1)
__device__ __forceinline__ u64 leaky2(u64 x) {
    const u64 SL = 0x3C23D70A3C23D70AULL;  // (0.01f, 0.01f)
    u64 s = mul2(x, SL);
    float xl, xh, sl, sh;
    unpack2(x, xl, xh); unpack2(s, sl, sh);
    return pack2(fmaxf(xl, sl), fmaxf(xh, sh));
}

struct Params { const float* p[20]; };  // [0..4]=ws_logs [5..9]=bs_logs [10..14]=ws_b [15..19]=bs_b

// Weights in CONSTANT memory: compile-time addresses -> uniform-const port,
// completely off the L1tex pipe.
__constant__ ulonglong2 CW[2][5][32];   // [(w2i,w2i),(w2i+1,w2i+1)] granules
__constant__ ulonglong2 CB[2][5][4];    // bias dup-pairs

// Device scratch the pack kernel writes; D2D-memcpy'd into CW/CB.
__device__ ulonglong2 GW_scratch[2][5][32];
__device__ ulonglong2 GB_scratch[2][5][4];

__global__ void pack_params_kernel(Params P)
{
    int tid = threadIdx.x;
    for (int idx = tid; idx < 320; idx += blockDim.x) {
        int m = idx / 160, r = idx % 160, l = r / 32, k = r % 32;
        int j = k / 4, i2 = k % 4;
        const float* Wp = P.p[m * 10 + l];
        float w0 = Wp[j * 8 + i2 * 2], w1 = Wp[j * 8 + i2 * 2 + 1];
        GW_scratch[m][l][k] = make_ulonglong2(pack2(w0, w0), pack2(w1, w1));
    }
    for (int idx = tid; idx < 40; idx += blockDim.x) {
        int m = idx / 20, r = idx % 20, l = r / 4, k = r % 4;
        const float* Bp = P.p[m * 10 + 5 + l];
        float b0 = Bp[2 * k], b1 = Bp[2 * k + 1];
        GB_scratch[m][l][k] = make_ulonglong2(pack2(b0, b0), pack2(b1, b1));
    }
}

// One 8->8 layer on TWO packed row-pairs; weights via constant memory with
// compile-time offsets (template M, L).
template <int M, int L>
__device__ __forceinline__ void layerC(
    const u64* in0, const u64* in1, u64* out0, u64* out1, bool act)
{
#pragma unroll
    for (int j2 = 0; j2 < 4; j2++) {
        ulonglong2 bias = CB[M][L][j2];
        u64 a0 = bias.x, a1 = bias.x;           // row j = 2*j2
        u64 c0 = bias.y, c1 = bias.y;           // row j = 2*j2+1
#pragma unroll
        for (int i2 = 0; i2 < 4; i2++) {
            ulonglong2 wa = CW[M][L][(2 * j2)     * 4 + i2];
            ulonglong2 wc = CW[M][L][(2 * j2 + 1) * 4 + i2];
            a0 = fma2(wa.x, in0[2 * i2],     a0);
            a1 = fma2(wa.x, in1[2 * i2],     a1);
            a0 = fma2(wa.y, in0[2 * i2 + 1], a0);
            a1 = fma2(wa.y, in1[2 * i2 + 1], a1);
            c0 = fma2(wc.x, in0[2 * i2],     c0);
            c1 = fma2(wc.x, in1[2 * i2],     c1);
            c0 = fma2(wc.y, in0[2 * i2 + 1], c0);
            c1 = fma2(wc.y, in1[2 * i2 + 1], c1);
        }
        out0[2 * j2]     = act ? leaky2(a0) : a0;
        out1[2 * j2]     = act ? leaky2(a1) : a1;
        out0[2 * j2 + 1] = act ? leaky2(c0) : c0;
        out1[2 * j2 + 1] = act ? leaky2(c1) : c1;
    }
}

template <int IOW>
__device__ __forceinline__ float4 ld4(const float* p) {
    if (IOW == 4) return *(const float4*)p;
    else if (IOW == 2) { float2 u = *(const float2*)p, v = *(const float2*)(p + 2);
                         return make_float4(u.x, u.y, v.x, v.y); }
    else return make_float4(p[0], p[1], p[2], p[3]);
}
template <int IOW>
__device__ __forceinline__ void st4(float* p, float4 v) {
    if (IOW == 4) *(float4*)p = v;
    else if (IOW == 2) { *(float2*)p = make_float2(v.x, v.y);
                         *(float2*)(p + 2) = make_float2(v.z, v.w); }
    else { p[0] = v.x; p[1] = v.y; p[2] = v.z; p[3] = v.w; }
}

// IOW: I/O width in floats per memory op (4 = float4, 2 = float2, 1 = scalar)
template <int IOW>
__global__ __launch_bounds__(128)
void affine_coupling_kernel(const float* __restrict__ z, float* __restrict__ out,
                            int batch)
{
    const int tid = threadIdx.x;
    const int lane = tid & 31;
    const int warp = tid >> 5;
    long long warpBase = ((long long)blockIdx.x * 4 + warp) * 128;
    if (warpBase >= batch) return;  // batch % 128 == 0 -> active warps are full

    // Each thread: 2 pairs = 4 rows. Pair p = (warpBase + 64p + lane, +32).
    int rA[2], rB[2];
    u64 zl[2][8];
#pragma unroll
    for (int p = 0; p < 2; p++) {
        rA[p] = (int)warpBase + p * 64 + lane;
        rB[p] = rA[p] + 32;
        const float* pa = z + (long long)rA[p] * 16;
        const float* pb = z + (long long)rB[p] * 16;
        // front halves only (zr deferred to epilogue to cut live registers)
        float4 a0 = ld4<IOW>(pa), a1 = ld4<IOW>(pa + 4);
        float4 b0 = ld4<IOW>(pb), b1 = ld4<IOW>(pb + 4);

        // left-half passthrough: store immediately
        float* oa = out + (long long)rA[p] * 16;
        float* ob = out + (long long)rB[p] * 16;
        st4<IOW>(oa, a0);     st4<IOW>(oa + 4, a1);
        st4<IOW>(ob, b0);     st4<IOW>(ob + 4, b1);

        zl[p][0] = pack2(a0.x, b0.x); zl[p][1] = pack2(a0.y, b0.y);
        zl[p][2] = pack2(a0.z, b0.z); zl[p][3] = pack2(a0.w, b0.w);
        zl[p][4] = pack2(a1.x, b1.x); zl[p][5] = pack2(a1.y, b1.y);
        zl[p][6] = pack2(a1.z, b1.z); zl[p][7] = pack2(a1.w, b1.w);
    }

    u64 s[2][8], t[2][8];

    // ---- log_s chain (m=0); zl stays alive for the b chain ----
    layerC<0, 0>(zl[0], zl[1], s[0], s[1], true);
    layerC<0, 1>(s[0], s[1], t[0], t[1], true);
    layerC<0, 2>(t[0], t[1], s[0], s[1], true);
    layerC<0, 3>(s[0], s[1], t[0], t[1], true);
    u64 ls[2][8];
    layerC<0, 4>(t[0], t[1], ls[0], ls[1], false);

    // convert to exp(log_s), packed
    u64 els[2][8];
#pragma unroll
    for (int p = 0; p < 2; p++)
#pragma unroll
        for (int j = 0; j < 8; j++) {
            float lA, lB; unpack2(ls[p][j], lA, lB);
            els[p][j] = pack2(__expf(lA), __expf(lB));
        }

    // ---- b chain (m=1); zl dies after layer 0 ----
    layerC<1, 0>(zl[0], zl[1], s[0], s[1], true);
    layerC<1, 1>(s[0], s[1], t[0], t[1], true);
    layerC<1, 2>(t[0], t[1], s[0], s[1], true);
    layerC<1, 3>(s[0], s[1], t[0], t[1], true);
    u64 bv[2][8];
    layerC<1, 4>(t[0], t[1], bv[0], bv[1], false);

    // ---- epilogue: load zr now, yr = exp(log_s) * zr + b ----
#pragma unroll
    for (int p = 0; p < 2; p++) {
        const float* pa = z + (long long)rA[p] * 16 + 8;
        const float* pb = z + (long long)rB[p] * 16 + 8;
        float4 a2 = ld4<IOW>(pa), a3 = ld4<IOW>(pa + 4);
        float4 b2 = ld4<IOW>(pb), b3 = ld4<IOW>(pb + 4);

        u64 zr[8];
        zr[0] = pack2(a2.x, b2.x); zr[1] = pack2(a2.y, b2.y);
        zr[2] = pack2(a2.z, b2.z); zr[3] = pack2(a2.w, b2.w);
        zr[4] = pack2(a3.x, b3.x); zr[5] = pack2(a3.y, b3.y);
        zr[6] = pack2(a3.z, b3.z); zr[7] = pack2(a3.w, b3.w);

        float yA[8], yB[8];
#pragma unroll
        for (int j = 0; j < 8; j++) {
            u64 y = fma2(els[p][j], zr[j], bv[p][j]);
            unpack2(y, yA[j], yB[j]);
        }
        float* oa = out + (long long)rA[p] * 16 + 8;
        float* ob = out + (long long)rB[p] * 16 + 8;
        st4<IOW>(oa,     make_float4(yA[0], yA[1], yA[2], yA[3]));
        st4<IOW>(oa + 4, make_float4(yA[4], yA[5], yA[6], yA[7]));
        st4<IOW>(ob,     make_float4(yB[0], yB[1], yB[2], yB[3]));
        st4<IOW>(ob + 4, make_float4(yB[4], yB[5], yB[6], yB[7]));
    }
}

extern "C" void kernel_launch(void* const* d_in, const int* in_sizes, int n_in,
                              void* d_out, int out_size)
{
    // ---- locate z: the (unique) huge input ----
    int zi = 0;
    for (int i = 0; i < n_in; i++) {
        if (in_sizes[i] > in_sizes[zi]) zi = i;
    }
    const float* z = (const float*)d_in[zi];
    long long batchLL = (long long)in_sizes[zi] / 16;
    int batch = (int)batchLL;
    float* out = (float*)d_out;

    // ---- build the 20 layer-parameter pointers, layout-adaptively ----
    Params P;
    if (n_in >= 21) {
        int k = 0;
        for (int i = 0; i < n_in && k < 20; i++) {
            if (i == zi) continue;
            P.p[k++] = (const float*)d_in[i];
        }
    } else {
        int wslot = 0, bslot = 0;  // 0 -> logs, 1 -> b
        for (int i = 0; i < n_in; i++) {
            if (i == zi) continue;
            const float* base = (const float*)d_in[i];
            int sz = in_sizes[i];
            if (sz == 320) {            // stacked weights (5,8,8)
                int m = (wslot++ == 0) ? 0 : 1;
                for (int l = 0; l < 5; l++) P.p[m * 10 + l] = base + 64 * l;
            } else if (sz == 40) {      // stacked biases (5,8)
                int m = (bslot++ == 0) ? 0 : 1;
                for (int l = 0; l < 5; l++) P.p[m * 10 + 5 + l] = base + 8 * l;
            }
        }
    }

    // prologue: pack dup-pairs into device scratch, then D2D-copy into the
    // constant bank. NOTE: must resolve the *device* address of the scratch
    // symbols — passing the symbol directly would use the host stub address.
    pack_params_kernel<<<1, 128>>>(P);
    void *gw_dev = nullptr, *gb_dev = nullptr;
    cudaGetSymbolAddress(&gw_dev, GW_scratch);
    cudaGetSymbolAddress(&gb_dev, GB_scratch);
    cudaMemcpyToSymbolAsync(CW, gw_dev, sizeof(CW), 0, cudaMemcpyDeviceToDevice, 0);
    cudaMemcpyToSymbolAsync(CB, gb_dev, sizeof(CB), 0, cudaMemcpyDeviceToDevice, 0);

    int rowsPerBlock = 512;                // 128 threads * 4 rows
    int grid = (int)((batchLL + rowsPerBlock - 1) / rowsPerBlock);

    uintptr_t mis = (uintptr_t)z | (uintptr_t)out;
    if ((mis & 15) == 0) {
        affine_coupling_kernel<4><<<grid, 128>>>(z, out, batch);
    } else if ((mis & 7) == 0) {
        affine_coupling_kernel<2><<<grid, 128>>>(z, out, batch);
    } else {
        affine_coupling_kernel<1><<<grid, 128>>>(z, out, batch);
    }
}